// round 9
// baseline (speedup 1.0000x reference)
#include <cuda_runtime.h>
#include <cuda_fp16.h>
#include <cstdint>

// y[m,n] = mask[m] ? x[m,:]·W_v[n,:] : x[m,:]·W_t[n,:]
// Mask-partitioned single GEMM, fp16 m16n8k16 mma.sync, fp32 accumulate.
// Both operands pre-packed in MMA fragment order in gmem. A is loaded
// DIRECTLY gmem->registers (no smem: removes the crossbar bottleneck),
// B via 4-stage cp.async smem pipeline. MMA-bound by design.

#define M_TOTAL 32768
#define K_DIM   1024
#define N_DIM   1024
#define BM 128
#define BN 128
#define BK 32
#define NK (K_DIM / BK)              // 32 k-panels
#define THREADS 128
#define M_PAD 32896                  // 257 tiles * 128
#define NMT (M_PAD / BM)             // 257

#define PANEL_H  4096                // halves per 8KB panel
#define APANEL_B 8192
#define BPANEL_B 8192
#define BSTAGES  4
#define DYN_SMEM (BSTAGES * BPANEL_B)  // 32 KB

// ------------------------------------------------------------- device state
__device__ __half g_x[(size_t)M_PAD * K_DIM];    // [mtile][kpanel][frag order]
__device__ __half g_wv[(size_t)N_DIM * K_DIM];   // [ntile][kpanel][frag order]
__device__ __half g_wt[(size_t)N_DIM * K_DIM];
__device__ int   g_perm[M_PAD];                  // slot -> source row (live only)
__device__ int   g_cv, g_ct;                     // visual / text counters
__device__ int   g_mask_is_u8;

// Slot map: visual rows -> [0, nv) ascending; dead gap [nv, nv+128);
// text rows -> [nv+128, M_PAD) (descending fill). Tile t is visual iff
// 128*t < nv. Exactness: nv + nt = 32768, M_PAD - nt = nv + 128.

// ------------------------------------------------------------- helpers
__device__ __forceinline__ bool mask_at(const unsigned char* m, int i) {
    return g_mask_is_u8 ? (m[i] != 0) : (((const int*)m)[i] != 0);
}

__device__ __forceinline__ uint32_t smem_u32(const void* p) {
    uint32_t a;
    asm("{ .reg .u64 t; cvta.to.shared.u64 t, %1; cvt.u32.u64 %0, t; }"
        : "=r"(a) : "l"(p));
    return a;
}

__device__ __forceinline__ void cp16(uint32_t saddr, const void* g) {
    asm volatile("cp.async.cg.shared.global [%0], [%1], 16;"
                 :: "r"(saddr), "l"(g) : "memory");
}

__device__ __forceinline__ void mma_f16(float* d, const uint32_t* a, const uint32_t* b) {
    asm volatile(
        "mma.sync.aligned.m16n8k16.row.col.f32.f16.f16.f32 "
        "{%0,%1,%2,%3}, {%4,%5,%6,%7}, {%8,%9}, {%0,%1,%2,%3};"
        : "+f"(d[0]), "+f"(d[1]), "+f"(d[2]), "+f"(d[3])
        : "r"(a[0]), "r"(a[1]), "r"(a[2]), "r"(a[3]), "r"(b[0]), "r"(b[1]));
}

// ------------------------------------------------------------- prep kernels
// K0: zero counters + detect mask dtype (1 block).
__global__ void k0_init(const unsigned char* __restrict__ m) {
    __shared__ int found;
    int tid = threadIdx.x;
    if (tid == 0) { found = 0; g_cv = 0; g_ct = 0; }
    __syncthreads();
    int local = 0;
    for (int i = tid; i < 8192; i += 1024)
        if (m[4 * i + 1] | m[4 * i + 2] | m[4 * i + 3]) local = 1;
    if (local) atomicOr(&found, 1);
    __syncthreads();
    if (tid == 0) g_mask_is_u8 = found;
}

// K12: one-pass slot assignment (no pre-count needed).
__global__ void k12_assign(const unsigned char* __restrict__ m) {
    int tid = threadIdx.x;
    int row = blockIdx.x * 256 + tid;
    int lane = tid & 31;
    bool mv = mask_at(m, row);
    unsigned bal = __ballot_sync(0xffffffffu, mv);
    int cv = __popc(bal);
    int lpv = __popc(bal & ((1u << lane) - 1));
    int lpt = lane - lpv;
    int baseV = 0, baseT = 0;
    if (lane == 0) {
        baseV = atomicAdd(&g_cv, cv);
        baseT = atomicAdd(&g_ct, 32 - cv);
    }
    baseV = __shfl_sync(0xffffffffu, baseV, 0);
    baseT = __shfl_sync(0xffffffffu, baseT, 0);
    int slot = mv ? (baseV + lpv) : (M_PAD - 1 - (baseT + lpt));
    g_perm[slot] = row;
}

// K34: merged prep. z=0: x gather+convert -> A panels (smem-staged, 16B
// coalesced reads). z=1 (first 16 x-blocks): weights -> B panels.
__global__ void k34_prep(const float* __restrict__ x,
                         const float* __restrict__ Wv,
                         const float* __restrict__ Wt)
{
    const int tid = threadIdx.x;
    const int kp  = blockIdx.y;
    const int kbase = kp * BK;

    if (blockIdx.z == 1) {
        int b = blockIdx.x;
        if (b >= 16) return;
        int which = b >> 3, nt = b & 7;
        const float* W = which ? Wt : Wv;
        __half* dst = (which ? g_wt : g_wv) + ((size_t)nt * NK + kp) * PANEL_H;
        #pragma unroll
        for (int q = 0; q < 2; q++) {
            int h0 = tid * 8 + q * 2048;
            __half vals[8];
            #pragma unroll
            for (int j = 0; j < 8; j++) {
                int h = h0 + j;
                int blk = h >> 7;
                int nb = blk >> 1, ks = blk & 1;
                int lane = (h >> 2) & 31;
                int v = h & 3;
                int grp = lane >> 2, qid = lane & 3;
                int n = nt * 128 + nb * 8 + grp;
                int k = kbase + ks * 16 + 2 * qid + 8 * (v >> 1) + (v & 1);
                vals[j] = __float2half_rn(W[(size_t)n * K_DIM + k]);
            }
            *(uint4*)(dst + h0) = *(const uint4*)vals;
        }
        return;
    }

    // x conversion: one (mt, kp) panel per block
    __shared__ float sx[BM * BK];
    __shared__ int sperm[BM];
    const int mt = blockIdx.x;
    const int nv = g_cv;
    if (tid < BM) {
        int slot = mt * BM + tid;
        bool live = (slot < nv) || (slot >= nv + BM);
        sperm[tid] = live ? g_perm[slot] : -1;
    }
    __syncthreads();

    #pragma unroll
    for (int i = 0; i < 4; i++) {
        int idx = i * 256 + tid;          // 0..1023
        int row = idx >> 3, q = idx & 7;
        int src = sperm[row];
        float4 v = (src >= 0)
            ? *(const float4*)(x + (size_t)src * K_DIM + kbase + q * 4)
            : make_float4(0.f, 0.f, 0.f, 0.f);
        *(float4*)(sx + row * BK + q * 4) = v;
    }
    __syncthreads();

    __half* dst = g_x + ((size_t)mt * NK + kp) * PANEL_H;
    #pragma unroll
    for (int i = 0; i < 2; i++) {
        int h0 = (i * 256 + tid) * 8;
        int b = h0 >> 8;
        int rb = b >> 1, ks = b & 1;
        int lane = (h0 >> 3) & 31;
        int grp = lane >> 2, qid = lane & 3;
        __half vals[8];
        #pragma unroll
        for (int reg = 0; reg < 4; reg++) {
            int row = rb * 16 + grp + 8 * (reg & 1);
            int k   = ks * 16 + 2 * qid + 8 * (reg >> 1);
            vals[reg * 2 + 0] = __float2half_rn(sx[row * BK + k]);
            vals[reg * 2 + 1] = __float2half_rn(sx[row * BK + k + 1]);
        }
        *(uint4*)(dst + h0) = *(const uint4*)vals;
    }
}

// ------------------------------------------------------------- GEMM
extern __shared__ __align__(128) char dsmem[];

__global__ __launch_bounds__(THREADS, 2)
void gemm_kernel(float* __restrict__ out)
{
    const int tid  = threadIdx.x;
    const int warp = tid >> 5;
    const int lane = tid & 31;
    const int grp  = lane >> 2;
    const int qid  = lane & 3;
    const int rb0  = (warp >> 1) * 4;        // A block base (64 rows)
    const int nb0  = (warp & 1) * 8;         // B block base (64 cols)
    const int nt   = blockIdx.x;
    const int mt   = blockIdx.y;
    const int blockM = mt * BM;
    const int blockN = nt * BN;

    const int nv = g_cv;
    const char* gA = (const char*)(g_x + (size_t)mt * NK * PANEL_H);
    const char* gB = (const char*)(((blockM < nv) ? g_wv : g_wt)
                                   + (size_t)nt * NK * PANEL_H);

    const uint32_t sbase = smem_u32(dsmem);

    float acc[4][8][4];
    #pragma unroll
    for (int i = 0; i < 4; i++)
        #pragma unroll
        for (int j = 0; j < 8; j++)
            #pragma unroll
            for (int c = 0; c < 4; c++) acc[i][j][c] = 0.f;

    uint32_t a[2][4][4];   // A frag double buffer (ks-step granularity)

    auto ALDG = [&](int s, int buf) {
        int kt = s >> 1, ks = s & 1;
        const char* p = gA + (size_t)kt * APANEL_B;
        #pragma unroll
        for (int i = 0; i < 4; i++) {
            uint4 v = *(const uint4*)(p + ((rb0 + i) * 2 + ks) * 512 + lane * 16);
            a[buf][i][0] = v.x; a[buf][i][1] = v.y;
            a[buf][i][2] = v.z; a[buf][i][3] = v.w;
        }
    };

    auto BISSUE = [&](int kt) {
        const uint32_t sst = sbase + (kt & (BSTAGES - 1)) * BPANEL_B;
        const char* srcB = gB + (size_t)kt * BPANEL_B;
        #pragma unroll
        for (int i = 0; i < 4; i++) {
            uint32_t off = (uint32_t)(i * 2048 + tid * 16);
            cp16(sst + off, srcB + off);
        }
        asm volatile("cp.async.commit_group;" ::: "memory");
    };

    // prologue
    BISSUE(0); BISSUE(1); BISSUE(2);
    ALDG(0, 0); ALDG(1, 1);

    for (int kt = 0; kt < NK; kt++) {
        // B(kt) must be complete below.
        if (kt < NK - 2)
            asm volatile("cp.async.wait_group 2;" ::: "memory");
        else if (kt == NK - 2)
            asm volatile("cp.async.wait_group 1;" ::: "memory");
        else
            asm volatile("cp.async.wait_group 0;" ::: "memory");
        __syncthreads();
        if (kt + 3 < NK) BISSUE(kt + 3);

        const char* sB = dsmem + (kt & (BSTAGES - 1)) * BPANEL_B;

        #pragma unroll
        for (int ks = 0; ks < 2; ks++) {
            const int s = kt * 2 + ks;
            const int buf = s & 1;
            uint32_t b[8][2];
            #pragma unroll
            for (int j = 0; j < 8; j++) {
                uint2 v = *(const uint2*)(sB + ((nb0 + j) * 2 + ks) * 256 + lane * 8);
                b[j][0] = v.x; b[j][1] = v.y;
            }
            #pragma unroll
            for (int i = 0; i < 4; i++)
                #pragma unroll
                for (int j = 0; j < 8; j++)
                    mma_f16(acc[i][j], a[buf][i], b[j]);
            if (s + 2 < 2 * NK) ALDG(s + 2, buf);   // refill after use (WAR)
        }
    }

    // epilogue: scatter live rows through perm
    #pragma unroll
    for (int i = 0; i < 4; i++) {
        int r = rb0 * 16 + i * 16 + grp;
        int s0 = blockM + r, s1 = blockM + r + 8;
        int d0 = ((s0 < nv) || (s0 >= nv + BM)) ? g_perm[s0] : -1;
        int d1 = ((s1 < nv) || (s1 >= nv + BM)) ? g_perm[s1] : -1;
        #pragma unroll
        for (int j = 0; j < 8; j++) {
            int col = blockN + nb0 * 8 + j * 8 + qid * 2;
            if (d0 >= 0)
                *(float2*)(out + (size_t)d0 * N_DIM + col) =
                    make_float2(acc[i][j][0], acc[i][j][1]);
            if (d1 >= 0)
                *(float2*)(out + (size_t)d1 * N_DIM + col) =
                    make_float2(acc[i][j][2], acc[i][j][3]);
        }
    }
}

// ------------------------------------------------------------- launch
extern "C" void kernel_launch(void* const* d_in, const int* in_sizes, int n_in,
                              void* d_out, int out_size)
{
    const float*         x    = (const float*)d_in[0];
    const unsigned char* mask = (const unsigned char*)d_in[1];
    const float*         Wv   = (const float*)d_in[2];
    const float*         Wt   = (const float*)d_in[3];
    float*               out  = (float*)d_out;

    k0_init<<<1, 1024>>>(mask);
    k12_assign<<<M_TOTAL / 256, 256>>>(mask);
    k34_prep<<<dim3(NMT, NK, 2), 256>>>(x, Wv, Wt);
    gemm_kernel<<<dim3(N_DIM / BN, NMT), THREADS, DYN_SMEM>>>(out);
}

// round 10
// speedup vs baseline: 1.0223x; 1.0223x over previous
#include <cuda_runtime.h>
#include <cuda_fp16.h>
#include <cstdint>

// y[m,n] = mask[m] ? x[m,:]·W_v[n,:] : x[m,:]·W_t[n,:]
// Mask-partitioned single GEMM, fp16 m16n8k16 mma.sync, fp32 accumulate.
// Operands pre-packed in MMA fragment order. A: direct gmem->reg LDG
// (no smem). B: 4-stage cp.async. This round: 256-thread CTAs, warp tile
// 64x32 (acc 64 regs) -> 16 warps/SM for latency hiding (occ 12.5->25%).

#define M_TOTAL 32768
#define K_DIM   1024
#define N_DIM   1024
#define BM 128
#define BN 128
#define BK 32
#define NK (K_DIM / BK)              // 32 k-panels
#define THREADS 256
#define M_PAD 32896                  // 257 tiles * 128
#define NMT (M_PAD / BM)             // 257

#define PANEL_H  4096                // halves per 8KB panel
#define APANEL_B 8192
#define BPANEL_B 8192
#define BSTAGES  4
#define DYN_SMEM (BSTAGES * BPANEL_B)  // 32 KB

// ------------------------------------------------------------- device state
__device__ __half g_x[(size_t)M_PAD * K_DIM];    // [mtile][kpanel][frag order]
__device__ __half g_wv[(size_t)N_DIM * K_DIM];   // [ntile][kpanel][frag order]
__device__ __half g_wt[(size_t)N_DIM * K_DIM];
__device__ int   g_perm[M_PAD];                  // slot -> source row (live only)
__device__ int   g_cv, g_ct;                     // visual / text counters
__device__ int   g_mask_is_u8;

// Slot map: visual -> [0, nv) ascending; dead gap [nv, nv+128);
// text -> [nv+128, M_PAD) descending. Tile t uses W_v iff 128*t < nv.

// ------------------------------------------------------------- helpers
__device__ __forceinline__ bool mask_at(const unsigned char* m, int i) {
    return g_mask_is_u8 ? (m[i] != 0) : (((const int*)m)[i] != 0);
}

__device__ __forceinline__ uint32_t smem_u32(const void* p) {
    uint32_t a;
    asm("{ .reg .u64 t; cvta.to.shared.u64 t, %1; cvt.u32.u64 %0, t; }"
        : "=r"(a) : "l"(p));
    return a;
}

__device__ __forceinline__ void cp16(uint32_t saddr, const void* g) {
    asm volatile("cp.async.cg.shared.global [%0], [%1], 16;"
                 :: "r"(saddr), "l"(g) : "memory");
}

__device__ __forceinline__ void mma_f16(float* d, const uint32_t* a, const uint32_t* b) {
    asm volatile(
        "mma.sync.aligned.m16n8k16.row.col.f32.f16.f16.f32 "
        "{%0,%1,%2,%3}, {%4,%5,%6,%7}, {%8,%9}, {%0,%1,%2,%3};"
        : "+f"(d[0]), "+f"(d[1]), "+f"(d[2]), "+f"(d[3])
        : "r"(a[0]), "r"(a[1]), "r"(a[2]), "r"(a[3]), "r"(b[0]), "r"(b[1]));
}

// ------------------------------------------------------------- prep kernels
__global__ void k0_init(const unsigned char* __restrict__ m) {
    __shared__ int found;
    int tid = threadIdx.x;
    if (tid == 0) { found = 0; g_cv = 0; g_ct = 0; }
    __syncthreads();
    int local = 0;
    for (int i = tid; i < 8192; i += 1024)
        if (m[4 * i + 1] | m[4 * i + 2] | m[4 * i + 3]) local = 1;
    if (local) atomicOr(&found, 1);
    __syncthreads();
    if (tid == 0) g_mask_is_u8 = found;
}

// K12: one-pass slot assignment.
__global__ void k12_assign(const unsigned char* __restrict__ m) {
    int tid = threadIdx.x;
    int row = blockIdx.x * 256 + tid;
    int lane = tid & 31;
    bool mv = mask_at(m, row);
    unsigned bal = __ballot_sync(0xffffffffu, mv);
    int cv = __popc(bal);
    int lpv = __popc(bal & ((1u << lane) - 1));
    int lpt = lane - lpv;
    int baseV = 0, baseT = 0;
    if (lane == 0) {
        baseV = atomicAdd(&g_cv, cv);
        baseT = atomicAdd(&g_ct, 32 - cv);
    }
    baseV = __shfl_sync(0xffffffffu, baseV, 0);
    baseT = __shfl_sync(0xffffffffu, baseT, 0);
    int slot = mv ? (baseV + lpv) : (M_PAD - 1 - (baseT + lpt));
    g_perm[slot] = row;
}

// K3: x gather + fp16 convert -> A panels (smem-staged 16B reads).
__global__ void k3_xconv(const float* __restrict__ x) {
    __shared__ float sx[BM * BK];
    __shared__ int sperm[BM];
    const int mt = blockIdx.x, kp = blockIdx.y;
    const int tid = threadIdx.x;
    const int kbase = kp * BK;
    const int nv = g_cv;
    if (tid < BM) {
        int slot = mt * BM + tid;
        bool live = (slot < nv) || (slot >= nv + BM);
        sperm[tid] = live ? g_perm[slot] : -1;
    }
    __syncthreads();

    #pragma unroll
    for (int i = 0; i < 4; i++) {
        int idx = i * 256 + tid;          // 0..1023
        int row = idx >> 3, q = idx & 7;
        int src = sperm[row];
        float4 v = (src >= 0)
            ? *(const float4*)(x + (size_t)src * K_DIM + kbase + q * 4)
            : make_float4(0.f, 0.f, 0.f, 0.f);
        *(float4*)(sx + row * BK + q * 4) = v;
    }
    __syncthreads();

    __half* dst = g_x + ((size_t)mt * NK + kp) * PANEL_H;
    #pragma unroll
    for (int i = 0; i < 2; i++) {
        int h0 = (i * 256 + tid) * 8;
        int b = h0 >> 8;
        int rb = b >> 1, ks = b & 1;
        int lane = (h0 >> 3) & 31;
        int grp = lane >> 2, qid = lane & 3;
        __half vals[8];
        #pragma unroll
        for (int reg = 0; reg < 4; reg++) {
            int row = rb * 16 + grp + 8 * (reg & 1);
            int k   = ks * 16 + 2 * qid + 8 * (reg >> 1);
            vals[reg * 2 + 0] = __float2half_rn(sx[row * BK + k]);
            vals[reg * 2 + 1] = __float2half_rn(sx[row * BK + k + 1]);
        }
        *(uint4*)(dst + h0) = *(const uint4*)vals;
    }
}

// K4: one weight matrix -> fp16 B panels in fragment order.
__global__ void k4_wconv(const float* __restrict__ W, int which) {
    const int nt = blockIdx.x, kp = blockIdx.y;
    __half* dst = (which ? g_wt : g_wv) + ((size_t)nt * NK + kp) * PANEL_H;
    const int tid = threadIdx.x;
    const int kbase = kp * BK;
    #pragma unroll
    for (int q = 0; q < 2; q++) {
        int h0 = tid * 8 + q * 2048;
        __half vals[8];
        #pragma unroll
        for (int j = 0; j < 8; j++) {
            int h = h0 + j;
            int blk = h >> 7;
            int nb = blk >> 1, ks = blk & 1;
            int lane = (h >> 2) & 31;
            int v = h & 3;
            int grp = lane >> 2, qid = lane & 3;
            int n = nt * 128 + nb * 8 + grp;
            int k = kbase + ks * 16 + 2 * qid + 8 * (v >> 1) + (v & 1);
            vals[j] = __float2half_rn(W[(size_t)n * K_DIM + k]);
        }
        *(uint4*)(dst + h0) = *(const uint4*)vals;
    }
}

// ------------------------------------------------------------- GEMM
extern __shared__ __align__(128) char dsmem[];

__global__ __launch_bounds__(THREADS, 2)
void gemm_kernel(float* __restrict__ out)
{
    const int tid  = threadIdx.x;
    const int warp = tid >> 5;
    const int lane = tid & 31;
    const int grp  = lane >> 2;
    const int qid  = lane & 3;
    const int rb0  = (warp >> 2) * 4;        // A 16-row block base (64 rows)
    const int nb0  = (warp & 3) * 4;         // B 8-col block base (32 cols)
    const int nt   = blockIdx.x;
    const int mt   = blockIdx.y;
    const int blockM = mt * BM;
    const int blockN = nt * BN;

    const int nv = g_cv;
    const char* gA = (const char*)(g_x + (size_t)mt * NK * PANEL_H);
    const char* gB = (const char*)(((blockM < nv) ? g_wv : g_wt)
                                   + (size_t)nt * NK * PANEL_H);

    const uint32_t sbase = smem_u32(dsmem);

    float acc[4][4][4];
    #pragma unroll
    for (int i = 0; i < 4; i++)
        #pragma unroll
        for (int j = 0; j < 4; j++)
            #pragma unroll
            for (int c = 0; c < 4; c++) acc[i][j][c] = 0.f;

    uint32_t a[2][4][4];   // A frag double buffer (ks-step granularity)

    auto ALDG = [&](int s, int buf) {
        int kt = s >> 1, ks = s & 1;
        const char* p = gA + (size_t)kt * APANEL_B;
        #pragma unroll
        for (int i = 0; i < 4; i++) {
            uint4 v = *(const uint4*)(p + ((rb0 + i) * 2 + ks) * 512 + lane * 16);
            a[buf][i][0] = v.x; a[buf][i][1] = v.y;
            a[buf][i][2] = v.z; a[buf][i][3] = v.w;
        }
    };

    auto BISSUE = [&](int kt) {
        const uint32_t sst = sbase + (kt & (BSTAGES - 1)) * BPANEL_B;
        const char* srcB = gB + (size_t)kt * BPANEL_B;
        #pragma unroll
        for (int i = 0; i < 2; i++) {
            uint32_t off = (uint32_t)(i * 4096 + tid * 16);
            cp16(sst + off, srcB + off);
        }
        asm volatile("cp.async.commit_group;" ::: "memory");
    };

    // prologue
    BISSUE(0); BISSUE(1); BISSUE(2);
    ALDG(0, 0); ALDG(1, 1);

    for (int kt = 0; kt < NK; kt++) {
        if (kt < NK - 2)
            asm volatile("cp.async.wait_group 2;" ::: "memory");
        else if (kt == NK - 2)
            asm volatile("cp.async.wait_group 1;" ::: "memory");
        else
            asm volatile("cp.async.wait_group 0;" ::: "memory");
        __syncthreads();
        if (kt + 3 < NK) BISSUE(kt + 3);

        const char* sB = dsmem + (kt & (BSTAGES - 1)) * BPANEL_B;

        #pragma unroll
        for (int ks = 0; ks < 2; ks++) {
            const int s = kt * 2 + ks;
            const int buf = s & 1;
            uint32_t b[4][2];
            #pragma unroll
            for (int j = 0; j < 4; j++) {
                uint2 v = *(const uint2*)(sB + ((nb0 + j) * 2 + ks) * 256 + lane * 8);
                b[j][0] = v.x; b[j][1] = v.y;
            }
            #pragma unroll
            for (int i = 0; i < 4; i++)
                #pragma unroll
                for (int j = 0; j < 4; j++)
                    mma_f16(acc[i][j], a[buf][i], b[j]);
            if (s + 2 < 2 * NK) ALDG(s + 2, buf);   // refill after use (WAR)
        }
    }

    // epilogue: scatter live rows through perm
    #pragma unroll
    for (int i = 0; i < 4; i++) {
        int r = (rb0 + i) * 16 + grp;
        int s0 = blockM + r, s1 = blockM + r + 8;
        int d0 = ((s0 < nv) || (s0 >= nv + BM)) ? g_perm[s0] : -1;
        int d1 = ((s1 < nv) || (s1 >= nv + BM)) ? g_perm[s1] : -1;
        #pragma unroll
        for (int j = 0; j < 4; j++) {
            int col = blockN + (nb0 + j) * 8 + qid * 2;
            if (d0 >= 0)
                *(float2*)(out + (size_t)d0 * N_DIM + col) =
                    make_float2(acc[i][j][0], acc[i][j][1]);
            if (d1 >= 0)
                *(float2*)(out + (size_t)d1 * N_DIM + col) =
                    make_float2(acc[i][j][2], acc[i][j][3]);
        }
    }
}

// ------------------------------------------------------------- launch
extern "C" void kernel_launch(void* const* d_in, const int* in_sizes, int n_in,
                              void* d_out, int out_size)
{
    const float*         x    = (const float*)d_in[0];
    const unsigned char* mask = (const unsigned char*)d_in[1];
    const float*         Wv   = (const float*)d_in[2];
    const float*         Wt   = (const float*)d_in[3];
    float*               out  = (float*)d_out;

    // 6 launches, GEMM last -> ncu (-s 5 -c 1) profiles the GEMM
    k0_init<<<1, 1024>>>(mask);
    k12_assign<<<M_TOTAL / 256, 256>>>(mask);
    k3_xconv<<<dim3(NMT, NK), 256>>>(x);
    k4_wconv<<<dim3(N_DIM / 128, NK), 256>>>(Wv, 0);
    k4_wconv<<<dim3(N_DIM / 128, NK), 256>>>(Wt, 1);
    gemm_kernel<<<dim3(N_DIM / BN, NMT), THREADS, DYN_SMEM>>>(out);
}